// round 2
// baseline (speedup 1.0000x reference)
#include <cuda_runtime.h>
#include <math.h>

// ---------------------------------------------------------------------------
// BiLSTM: B=32, T=512, D=512, H=512.
//   Kernel 0: transpose x[b][t][d] -> g_xT[t][d][b]
//   Kernel 1: xg[dir][t][g][b] = sum_d x[b][t][d]*W_ih[dir][g][d] + b_ih+b_hh
//   Kernel 2: persistent recurrence (128 blocks, software grid barrier/step)
// ---------------------------------------------------------------------------

#define BB 32
#define TT 512
#define DD 512
#define HH 512
#define G4 2048           // 4*H
#define NBLK_REC 128

// Scratch (device globals; no allocation allowed)
__device__ float g_xT[(size_t)TT * DD * BB];             // 33.5 MB  [t][d][b]
__device__ float g_xg[(size_t)2 * TT * G4 * BB];         // 256 MB   [dir][t][g][b]
__device__ float g_h[(size_t)2 * 2 * HH * BB];           // [buf][dir][j][b]
__device__ unsigned int g_bar;

__device__ __forceinline__ float sigmoidf_(float x) {
    return 1.0f / (1.0f + expf(-x));
}

// 4-row x 32-batch dot product over K=512.
// sW: 32 rows x 512 (row r = q*8 + w).  sV: [k*32 + b] (b fastest, conflict-free).
__device__ __forceinline__ void dot4(const float* __restrict__ sW,
                                     const float* __restrict__ sV,
                                     int w, int lane, float a[4]) {
    const float* w0 = sW + (size_t)(w     ) * 512;
    const float* w1 = sW + (size_t)(w +  8) * 512;
    const float* w2 = sW + (size_t)(w + 16) * 512;
    const float* w3 = sW + (size_t)(w + 24) * 512;
    float a0 = 0.f, a1 = 0.f, a2 = 0.f, a3 = 0.f;
#pragma unroll 4
    for (int k = 0; k < 512; k += 4) {
        float4 v0 = *(const float4*)(w0 + k);
        float4 v1 = *(const float4*)(w1 + k);
        float4 v2 = *(const float4*)(w2 + k);
        float4 v3 = *(const float4*)(w3 + k);
        float h0 = sV[(k + 0) * 32 + lane];
        float h1 = sV[(k + 1) * 32 + lane];
        float h2 = sV[(k + 2) * 32 + lane];
        float h3 = sV[(k + 3) * 32 + lane];
        a0 = fmaf(v0.x, h0, a0); a0 = fmaf(v0.y, h1, a0);
        a0 = fmaf(v0.z, h2, a0); a0 = fmaf(v0.w, h3, a0);
        a1 = fmaf(v1.x, h0, a1); a1 = fmaf(v1.y, h1, a1);
        a1 = fmaf(v1.z, h2, a1); a1 = fmaf(v1.w, h3, a1);
        a2 = fmaf(v2.x, h0, a2); a2 = fmaf(v2.y, h1, a2);
        a2 = fmaf(v2.z, h2, a2); a2 = fmaf(v2.w, h3, a2);
        a3 = fmaf(v3.x, h0, a3); a3 = fmaf(v3.y, h1, a3);
        a3 = fmaf(v3.z, h2, a3); a3 = fmaf(v3.w, h3, a3);
    }
    a[0] = a0; a[1] = a1; a[2] = a2; a[3] = a3;
}

// ---------------------------------------------------------------------------
// Kernel: init (reset barrier + zero h buffers each launch; graph replays)
// ---------------------------------------------------------------------------
__global__ void init_kernel() {
    int i = blockIdx.x * blockDim.x + threadIdx.x;
    if (i == 0) g_bar = 0u;
    if (i < 2 * 2 * HH * BB) g_h[i] = 0.f;
}

// ---------------------------------------------------------------------------
// Kernel 0: transpose x[b][t][d] -> g_xT[t][d][b]
// grid (T, D/32), 256 threads
// ---------------------------------------------------------------------------
__global__ void transpose_x(const float* __restrict__ x) {
    int t = blockIdx.x;
    int d0 = blockIdx.y * 32;
    __shared__ float tile[32][33];
    int tid = threadIdx.x;
    {
        int b = tid >> 3;
        int dq = (tid & 7) * 4;
        float4 v = *(const float4*)(x + ((size_t)(b * TT + t)) * DD + d0 + dq);
        tile[b][dq + 0] = v.x; tile[b][dq + 1] = v.y;
        tile[b][dq + 2] = v.z; tile[b][dq + 3] = v.w;
    }
    __syncthreads();
    {
        int d = tid >> 3;
        int bq = (tid & 7) * 4;
        float4 o;
        o.x = tile[bq + 0][d]; o.y = tile[bq + 1][d];
        o.z = tile[bq + 2][d]; o.w = tile[bq + 3][d];
        *(float4*)(g_xT + ((size_t)(t * DD + d0 + d)) * 32 + bq) = o;
    }
}

// ---------------------------------------------------------------------------
// Kernel 1: xg precompute.  grid (T, 128): y covers {dir(2) x 64 gate tiles}
// smem: sW 64KB + sX 64KB = 128KB dynamic
// ---------------------------------------------------------------------------
__global__ void __launch_bounds__(256, 1)
xg_kernel(const float* __restrict__ Wihf, const float* __restrict__ Wihb,
          const float* __restrict__ bihf, const float* __restrict__ bhhf,
          const float* __restrict__ bihb, const float* __restrict__ bhhb) {
    extern __shared__ float smem[];
    float* sW = smem;              // 32*512
    float* sX = smem + 32 * 512;   // 512*32
    int t = blockIdx.x;
    int ry = blockIdx.y;
    int dir = ry >> 6;
    int gbase = (ry & 63) * 32;
    const float* Wih = dir ? Wihb : Wihf;
    const float* bih = dir ? bihb : bihf;
    const float* bhh = dir ? bhhb : bhhf;
    int tid = threadIdx.x;
    {   // W tile: 32 consecutive rows -> contiguous 64KB
        const float4* src = (const float4*)(Wih + (size_t)gbase * DD);
        float4* dst = (float4*)sW;
        for (int i = tid; i < 32 * 128; i += 256) dst[i] = src[i];
    }
    {   // x_t tile
        const float4* src = (const float4*)(g_xT + (size_t)t * DD * 32);
        float4* dst = (float4*)sX;
        for (int i = tid; i < 4096; i += 256) dst[i] = src[i];
    }
    __syncthreads();
    int w = tid >> 5, lane = tid & 31;
    float a[4];
    dot4(sW, sX, w, lane, a);
    float* outp = g_xg + (((size_t)dir * TT + t) * G4 + gbase) * 32;
#pragma unroll
    for (int q = 0; q < 4; q++) {
        int r = q * 8 + w;
        int g = gbase + r;
        outp[(size_t)r * 32 + lane] = a[q] + bih[g] + bhh[g];
    }
}

// ---------------------------------------------------------------------------
// Software grid barrier (all NBLK_REC blocks resident: 1 block/SM forced by smem)
// ---------------------------------------------------------------------------
__device__ __forceinline__ void gsync(unsigned target) {
    __syncthreads();
    if (threadIdx.x == 0) {
        __threadfence();
        atomicAdd(&g_bar, 1u);
        while (*((volatile unsigned int*)&g_bar) < target) { }
        __threadfence();
    }
    __syncthreads();
}

// ---------------------------------------------------------------------------
// Kernel 2: persistent recurrence. 128 blocks x 256 threads.
// Block = (dir, 8 hidden units). Warp w owns unit j = jbase+w: rows i,f,g,o.
// lane = batch. c,h live in registers for all 512 steps.
// smem: sW 64KB (W_hh slice, loaded once) + sH 64KB (h broadcast, per step)
// ---------------------------------------------------------------------------
__global__ void __launch_bounds__(256, 1)
rec_kernel(const float* __restrict__ Whhf, const float* __restrict__ Whhb,
           const int* __restrict__ lengths, float* __restrict__ out) {
    extern __shared__ float smem[];
    float* sW = smem;
    float* sH = smem + 32 * 512;
    __shared__ float sOut[32][8];

    int blk = blockIdx.x;
    int dir = blk >> 6;
    int jbase = (blk & 63) * 8;
    int tid = threadIdx.x, w = tid >> 5, lane = tid & 31;
    const float* Whh = dir ? Whhb : Whhf;

    // Load W_hh slice once: local row r = q*8+ju  ->  global row q*512 + jbase + ju
    for (int i = tid; i < 32 * 128; i += 256) {
        int r = i >> 7, kc = i & 127;
        int q = r >> 3, ju = r & 7;
        ((float4*)sW)[i] = ((const float4*)Whh)[(size_t)(q * HH + jbase + ju) * 128 + kc];
    }

    int mylen = lengths[lane];
    int j = jbase + w;
    float c = 0.f, h = 0.f;
    const float* xgd = g_xg + (size_t)dir * TT * G4 * 32;

    for (int s = 0; s < TT; s++) {
        int t = dir ? (TT - 1 - s) : s;
        int buf = s & 1;
        // broadcast h state for this direction into smem
        {
            const float4* src = (const float4*)(g_h + (size_t)(buf * 2 + dir) * HH * 32);
            float4* dst = (float4*)sH;
            for (int i = tid; i < 4096; i += 256) dst[i] = src[i];
        }
        __syncthreads();

        // xg for this (t, unit, lane): 4 coalesced loads, overlap with dot
        const float* xgt = xgd + (size_t)t * G4 * 32;
        float xi  = xgt[(0 * HH + j) * 32 + lane];
        float xf  = xgt[(1 * HH + j) * 32 + lane];
        float xg_ = xgt[(2 * HH + j) * 32 + lane];
        float xo  = xgt[(3 * HH + j) * 32 + lane];

        float a[4];
        dot4(sW, sH, w, lane, a);

        float gi = sigmoidf_(xi + a[0]);
        float gf = sigmoidf_(xf + a[1]);
        float gg = tanhf(xg_ + a[2]);
        float go = sigmoidf_(xo + a[3]);
        float cn = gf * c + gi * gg;
        float hn = go * tanhf(cn);
        if (t < mylen) { c = cn; h = hn; }   // mask: keep prev state on padding

        // publish h for next step (coalesced) into other buffer
        g_h[((size_t)((buf ^ 1) * 2 + dir) * HH + j) * 32 + lane] = h;

        // stage output tile and write coalesced 32B/row
        sOut[lane][w] = h;
        __syncthreads();
        if (tid < 64) {
            int b = tid >> 1, half = tid & 1;
            float4 v;
            v.x = sOut[b][half * 4 + 0]; v.y = sOut[b][half * 4 + 1];
            v.z = sOut[b][half * 4 + 2]; v.w = sOut[b][half * 4 + 3];
            *(float4*)(out + ((size_t)(b * TT + t)) * 1024 + dir * HH + jbase + half * 4) = v;
        }

        gsync((unsigned)(s + 1) * NBLK_REC);
    }
}

// ---------------------------------------------------------------------------
// Launch
// ---------------------------------------------------------------------------
extern "C" void kernel_launch(void* const* d_in, const int* in_sizes, int n_in,
                              void* d_out, int out_size) {
    const float* x      = (const float*)d_in[0];
    const int*   lens   = (const int*)  d_in[1];
    const float* W_ih_f = (const float*)d_in[2];
    const float* W_hh_f = (const float*)d_in[3];
    const float* b_ih_f = (const float*)d_in[4];
    const float* b_hh_f = (const float*)d_in[5];
    const float* W_ih_b = (const float*)d_in[6];
    const float* W_hh_b = (const float*)d_in[7];
    const float* b_ih_b = (const float*)d_in[8];
    const float* b_hh_b = (const float*)d_in[9];
    float* out = (float*)d_out;

    cudaFuncSetAttribute(xg_kernel,  cudaFuncAttributeMaxDynamicSharedMemorySize, 131072);
    cudaFuncSetAttribute(rec_kernel, cudaFuncAttributeMaxDynamicSharedMemorySize, 131072);

    init_kernel<<<256, 256>>>();
    transpose_x<<<dim3(TT, DD / 32), 256>>>(x);
    xg_kernel<<<dim3(TT, 128), 256, 131072>>>(W_ih_f, W_ih_b, b_ih_f, b_hh_f, b_ih_b, b_hh_b);
    rec_kernel<<<NBLK_REC, 256, 131072>>>(W_hh_f, W_hh_b, lens, out);
}